// round 4
// baseline (speedup 1.0000x reference)
#include <cuda_runtime.h>
#include <cstdint>

#define NL0 8000
#define NL1 4000
#define NL2 2000
#define DIM 128
#define XCOLS 384

// ---------------- scratch (device globals: allocation-free rule) ----------------
__device__ float g_X0[NL0 * XCOLS];
__device__ float g_X1[NL1 * XCOLS];
__device__ float g_X2[NL2 * XCOLS];
__device__ float g_S0[NL0 * XCOLS];
__device__ float g_S1[NL1 * XCOLS];
__device__ float g_S2[NL2 * XCOLS];
__device__ float g_T0[NL0 * XCOLS];
__device__ float g_T1[NL1 * XCOLS];
__device__ float g_T2[NL2 * XCOLS];

// ---------------- helpers ----------------
__device__ __forceinline__ uint32_t f2tf(float x) {
    uint32_t u;
    asm("cvt.rna.tf32.f32 %0, %1;" : "=r"(u) : "f"(x));
    return u;
}

#define BM 128
#define BN 128
#define BK 32
#define ASTRIDE 36   // 128x32 A tile, padded: frag-read bank = (4g + t4) -> conflict-free
#define BSTRIDE 136  // 32x128 B tile, padded: frag-read bank = (8*t4 + g) -> conflict-free

struct SmemT {
    uint32_t As[BM * ASTRIDE];
    uint32_t Bs[BK * BSTRIDE];
};

// Generic C = A(MxK, row-major, lda) @ B(KxN-block, row-major, ldb) tf32 GEMM body.
// One 128x128 output tile per block; 256 threads, 8 warps (2x4), warp tile 64x32,
// 4x4 grid of m16n8k8 mma per warp per k-step.
__device__ __forceinline__ void gemm_body(
    const float* __restrict__ A, int lda,
    const float* __restrict__ B, int ldb,
    float* __restrict__ C, int ldc,
    int M, int K, int bm, int bn, SmemT& sm)
{
    const int tid  = threadIdx.x;
    const int wid  = tid >> 5;
    const int lane = tid & 31;
    const int wm = (wid >> 2) * 64;   // warp row base: 0 or 64
    const int wn = (wid & 3) * 32;    // warp col base: 0,32,64,96
    const int g  = lane >> 2;         // groupID 0..7
    const int t4 = lane & 3;          // threadID_in_group 0..3

    float acc[4][4][4];
#pragma unroll
    for (int a = 0; a < 4; a++)
#pragma unroll
        for (int b = 0; b < 4; b++)
#pragma unroll
            for (int c = 0; c < 4; c++) acc[a][b][c] = 0.f;

    const int ktiles = (K + BK - 1) / BK;
    for (int kt = 0; kt < ktiles; ++kt) {
        const int kbase = kt * BK;
        // ---- load A tile 128x32 (4 float4 / thread), convert to tf32 ----
#pragma unroll
        for (int i = 0; i < 4; ++i) {
            int idx = tid + i * 256;
            int row = idx >> 3;
            int c4  = (idx & 7) << 2;
            float4 v = make_float4(0.f, 0.f, 0.f, 0.f);
            int grow = bm + row;
            int gk   = kbase + c4;
            if (grow < M && gk < K)
                v = *reinterpret_cast<const float4*>(A + (size_t)grow * lda + gk);
            uint32_t* d = &sm.As[row * ASTRIDE + c4];
            d[0] = f2tf(v.x); d[1] = f2tf(v.y); d[2] = f2tf(v.z); d[3] = f2tf(v.w);
        }
        // ---- load B tile 32x128 ----
#pragma unroll
        for (int i = 0; i < 4; ++i) {
            int idx = tid + i * 256;
            int row = idx >> 5;
            int c4  = (idx & 31) << 2;
            float4 v = make_float4(0.f, 0.f, 0.f, 0.f);
            int gk = kbase + row;
            if (gk < K)
                v = *reinterpret_cast<const float4*>(B + (size_t)gk * ldb + bn + c4);
            uint32_t* d = &sm.Bs[row * BSTRIDE + c4];
            d[0] = f2tf(v.x); d[1] = f2tf(v.y); d[2] = f2tf(v.z); d[3] = f2tf(v.w);
        }
        __syncthreads();
        // ---- 4 k-steps of k=8 ----
#pragma unroll
        for (int ks = 0; ks < 4; ++ks) {
            const int k0 = ks * 8;
            uint32_t af[4][4], bf[4][2];
#pragma unroll
            for (int mt = 0; mt < 4; ++mt) {
                const uint32_t* p  = &sm.As[(wm + mt * 16 + g) * ASTRIDE + k0 + t4];
                const uint32_t* p8 = p + 8 * ASTRIDE;
                af[mt][0] = p[0];   // (row g,     col t4)
                af[mt][1] = p8[0];  // (row g+8,   col t4)
                af[mt][2] = p[4];   // (row g,     col t4+4)
                af[mt][3] = p8[4];  // (row g+8,   col t4+4)
            }
#pragma unroll
            for (int nt = 0; nt < 4; ++nt) {
                const uint32_t* p = &sm.Bs[(k0 + t4) * BSTRIDE + wn + nt * 8 + g];
                bf[nt][0] = p[0];            // (k t4,   n g)
                bf[nt][1] = p[4 * BSTRIDE];  // (k t4+4, n g)
            }
#pragma unroll
            for (int mt = 0; mt < 4; ++mt)
#pragma unroll
                for (int nt = 0; nt < 4; ++nt)
                    asm volatile(
                        "mma.sync.aligned.m16n8k8.row.col.f32.tf32.tf32.f32 "
                        "{%0,%1,%2,%3}, {%4,%5,%6,%7}, {%8,%9}, {%0,%1,%2,%3};\n"
                        : "+f"(acc[mt][nt][0]), "+f"(acc[mt][nt][1]),
                          "+f"(acc[mt][nt][2]), "+f"(acc[mt][nt][3])
                        : "r"(af[mt][0]), "r"(af[mt][1]), "r"(af[mt][2]), "r"(af[mt][3]),
                          "r"(bf[nt][0]), "r"(bf[nt][1]));
        }
        __syncthreads();
    }
    // ---- store C ----
#pragma unroll
    for (int mt = 0; mt < 4; ++mt) {
        int r0 = bm + wm + mt * 16 + g;
#pragma unroll
        for (int nt = 0; nt < 4; ++nt) {
            int c0 = bn + wn + nt * 8 + 2 * t4;
            if (r0 < M)
                *reinterpret_cast<float2*>(C + (size_t)r0 * ldc + c0) =
                    make_float2(acc[mt][nt][0], acc[mt][nt][1]);
            if (r0 + 8 < M)
                *reinterpret_cast<float2*>(C + (size_t)(r0 + 8) * ldc + c0) =
                    make_float2(acc[mt][nt][2], acc[mt][nt][3]);
        }
    }
}

// ---------------- build X_i = [x0->i | x1->i | x2->i] ----------------
// Dense/gathered columns + zero-fill of scatter targets.
__global__ void fill_x_kernel(const float* __restrict__ h0, const float* __restrict__ h1,
                              const float* __restrict__ h2, const int* __restrict__ idx0,
                              const int* __restrict__ idx1)
{
    int m = blockIdx.x;
    int t = threadIdx.x;       // 0..95
    int seg = t >> 5;          // which 128-col block (source level j)
    int c4 = (t & 31) << 2;
    float4 v = make_float4(0.f, 0.f, 0.f, 0.f);
    if (m < NL0) {
        if (seg == 0) v = *reinterpret_cast<const float4*>(h0 + (size_t)m * DIM + c4);
        *reinterpret_cast<float4*>(g_X0 + (size_t)m * XCOLS + seg * DIM + c4) = v;
    } else if (m < NL0 + NL1) {
        int r = m - NL0;
        if (seg == 0)      v = *reinterpret_cast<const float4*>(h0 + (size_t)idx0[r] * DIM + c4);
        else if (seg == 1) v = *reinterpret_cast<const float4*>(h1 + (size_t)r * DIM + c4);
        *reinterpret_cast<float4*>(g_X1 + (size_t)r * XCOLS + seg * DIM + c4) = v;
    } else {
        int r = m - NL0 - NL1;
        if (seg == 0)      v = *reinterpret_cast<const float4*>(h0 + (size_t)idx0[idx1[r]] * DIM + c4);
        else if (seg == 1) v = *reinterpret_cast<const float4*>(h1 + (size_t)idx1[r] * DIM + c4);
        else               v = *reinterpret_cast<const float4*>(h2 + (size_t)r * DIM + c4);
        *reinterpret_cast<float4*>(g_X2 + (size_t)r * XCOLS + seg * DIM + c4) = v;
    }
}

// Scatters (indices are unique -> no atomics). Must run AFTER fill_x zeroed targets.
__global__ void scatter_kernel(const float* __restrict__ h1, const float* __restrict__ h2,
                               const int* __restrict__ idx0, const int* __restrict__ idx1)
{
    int b = blockIdx.x;        // 0..7999
    int c4 = threadIdx.x << 2; // 32 threads x float4 = 128 cols
    float* dst;
    const float* src;
    if (b < NL1) {                       // h1 -> level0, cols [128,256)
        dst = g_X0 + (size_t)idx0[b] * XCOLS + DIM;
        src = h1 + (size_t)b * DIM;
    } else if (b < NL1 + NL2) {          // h2 -> level0, cols [256,384)
        int r = b - NL1;
        dst = g_X0 + (size_t)idx0[idx1[r]] * XCOLS + 2 * DIM;
        src = h2 + (size_t)r * DIM;
    } else {                             // h2 -> level1, cols [256,384)
        int r = b - NL1 - NL2;
        dst = g_X1 + (size_t)idx1[r] * XCOLS + 2 * DIM;
        src = h2 + (size_t)r * DIM;
    }
    *reinterpret_cast<float4*>(dst + c4) = *reinterpret_cast<const float4*>(src + c4);
}

// ---------------- stage 1: S_i = adj_i @ X_i ----------------
// grid: (x = n-block 0..2, y = m-block 0..62, z = level). x-fastest ordering keeps
// the 3 n-blocks sharing an adj row-panel adjacent -> adj read ~once from DRAM.
__global__ void __launch_bounds__(256) stage1_kernel(
    const float* __restrict__ adj0, const float* __restrict__ adj1,
    const float* __restrict__ adj2)
{
    __shared__ SmemT sm;
    int lvl = blockIdx.z;
    const float* A; float* Xp; float* Sp; int n;
    if (lvl == 0)      { A = adj0; Xp = g_X0; Sp = g_S0; n = NL0; }
    else if (lvl == 1) { A = adj1; Xp = g_X1; Sp = g_S1; n = NL1; }
    else               { A = adj2; Xp = g_X2; Sp = g_S2; n = NL2; }
    int bm = blockIdx.y * BM;
    if (bm >= n) return;
    int bn = blockIdx.x * BN;
    gemm_body(A, n, Xp, XCOLS, Sp, XCOLS, n, n, bm, bn, sm);
}

// ---------------- stage 2: T_i[:, 128j:128j+128] = S_i[:, 128j:] @ W[i,j] ----------------
__global__ void __launch_bounds__(256) stage2_kernel(const float* __restrict__ Ws)
{
    __shared__ SmemT sm;
    int i = blockIdx.z, j = blockIdx.y;
    const float* Sp; float* Tp; int n;
    if (i == 0)      { Sp = g_S0; Tp = g_T0; n = NL0; }
    else if (i == 1) { Sp = g_S1; Tp = g_T1; n = NL1; }
    else             { Sp = g_S2; Tp = g_T2; n = NL2; }
    int bm = blockIdx.x * BM;
    if (bm >= n) return;
    gemm_body(Sp + j * DIM, XCOLS,
              Ws + (size_t)(i * 3 + j) * DIM * DIM, DIM,
              Tp + j * DIM, XCOLS, n, DIM, bm, 0, sm);
}

// ---------------- final: out_i = sum_j relu(T_ij + b_ij) ----------------
__global__ void final_kernel(const float* __restrict__ bs, float* __restrict__ out)
{
    int m = blockIdx.x;        // global row 0..13999
    int c4 = threadIdx.x << 2;
    const float* T; int lvl;
    if (m < NL0)            { lvl = 0; T = g_T0 + (size_t)m * XCOLS; }
    else if (m < NL0 + NL1) { lvl = 1; T = g_T1 + (size_t)(m - NL0) * XCOLS; }
    else                    { lvl = 2; T = g_T2 + (size_t)(m - NL0 - NL1) * XCOLS; }
    float4 acc = make_float4(0.f, 0.f, 0.f, 0.f);
#pragma unroll
    for (int j = 0; j < 3; ++j) {
        float4 v = *reinterpret_cast<const float4*>(T + j * DIM + c4);
        float4 b = *reinterpret_cast<const float4*>(bs + (size_t)(lvl * 3 + j) * DIM + c4);
        acc.x += fmaxf(v.x + b.x, 0.f);
        acc.y += fmaxf(v.y + b.y, 0.f);
        acc.z += fmaxf(v.z + b.z, 0.f);
        acc.w += fmaxf(v.w + b.w, 0.f);
    }
    *reinterpret_cast<float4*>(out + (size_t)m * DIM + c4) = acc;
}

// ---------------- launch ----------------
extern "C" void kernel_launch(void* const* d_in, const int* in_sizes, int n_in,
                              void* d_out, int out_size)
{
    const float* adj0 = (const float*)d_in[0];
    const float* adj1 = (const float*)d_in[1];
    const float* adj2 = (const float*)d_in[2];
    const float* h0   = (const float*)d_in[3];
    const float* h1   = (const float*)d_in[4];
    const float* h2   = (const float*)d_in[5];
    const int*   idx0 = (const int*)d_in[6];
    const int*   idx1 = (const int*)d_in[7];
    const float* Ws   = (const float*)d_in[8];
    const float* bs   = (const float*)d_in[9];
    float* out = (float*)d_out;

    fill_x_kernel<<<NL0 + NL1 + NL2, 96>>>(h0, h1, h2, idx0, idx1);
    scatter_kernel<<<NL1 + NL2 + NL2, 32>>>(h1, h2, idx0, idx1);
    stage1_kernel<<<dim3(3, (NL0 + BM - 1) / BM, 3), 256>>>(adj0, adj1, adj2);
    stage2_kernel<<<dim3((NL0 + BM - 1) / BM, 3, 3), 256>>>(Ws);
    final_kernel<<<NL0 + NL1 + NL2, 32>>>(bs, out);
}

// round 6
// speedup vs baseline: 1.1420x; 1.1420x over previous
#include <cuda_runtime.h>
#include <cstdint>

#define NL0 8000
#define NL1 4000
#define NL2 2000
#define DIM 128
#define XCOLS 384

#define BM 128
#define BN 128
#define BK 32
#define ASTRIDE 36    // A tile 128x32 padded: frag bank = 4g+t4 -> conflict-free
#define BSTRIDE 136   // B tile 32x128 padded: frag bank = 8t4+g -> conflict-free
#define NSTAGES 3
#define STAGE_WORDS (BM * ASTRIDE + BK * BSTRIDE)   // 8960 words
#define SMEM_WORDS (NSTAGES * STAGE_WORDS)          // 26880 words
#define SMEM_BYTES (SMEM_WORDS * 4)                 // 107520 B
#define AE_STRIDE 132 // epilogue S-tile 128x128 padded: frag bank = 4g+t4

// ---------------- scratch (device globals: allocation-free rule) ----------------
__device__ float g_X0[NL0 * XCOLS];
__device__ float g_X1[NL1 * XCOLS];
__device__ float g_X2[NL2 * XCOLS];

// ---------------- helpers ----------------
__device__ __forceinline__ uint32_t f2tf(float x) {
    uint32_t u;
    asm("cvt.rna.tf32.f32 %0, %1;" : "=r"(u) : "f"(x));
    return u;
}
__device__ __forceinline__ float tf32r(float x) { return __uint_as_float(f2tf(x)); }

__device__ __forceinline__ void cp16(uint32_t dst, const float* src, bool p) {
    int sz = p ? 16 : 0;
    asm volatile("cp.async.cg.shared.global [%0], [%1], 16, %2;\n"
                 :: "r"(dst), "l"(src), "r"(sz));
}
#define CP_COMMIT() asm volatile("cp.async.commit_group;\n")
#define CP_WAIT1()  asm volatile("cp.async.wait_group 1;\n" ::: "memory")
#define CP_WAIT0()  asm volatile("cp.async.wait_group 0;\n" ::: "memory")

__device__ __forceinline__ void redadd(float* p, float v) {
    asm volatile("red.global.add.f32 [%0], %1;" :: "l"(p), "f"(v) : "memory");
}

#define MMA_TF32(d, a, b)                                                        \
    asm volatile(                                                                \
        "mma.sync.aligned.m16n8k8.row.col.f32.tf32.tf32.f32 "                    \
        "{%0,%1,%2,%3}, {%4,%5,%6,%7}, {%8,%9}, {%0,%1,%2,%3};\n"                \
        : "+f"(d[0]), "+f"(d[1]), "+f"(d[2]), "+f"(d[3])                         \
        : "r"(a[0]), "r"(a[1]), "r"(a[2]), "r"(a[3]), "r"(b[0]), "r"(b[1]))

// ---------------- build X_i = [x0->i | x1->i | x2->i] (tf32-prerounded) -------
__global__ void fill_x_kernel(const float* __restrict__ h0, const float* __restrict__ h1,
                              const float* __restrict__ h2, const int* __restrict__ idx0,
                              const int* __restrict__ idx1)
{
    int m = blockIdx.x;
    int t = threadIdx.x;       // 0..95
    int seg = t >> 5;
    int c4 = (t & 31) << 2;
    float4 v = make_float4(0.f, 0.f, 0.f, 0.f);
    float* dst;
    if (m < NL0) {
        if (seg == 0) v = *reinterpret_cast<const float4*>(h0 + (size_t)m * DIM + c4);
        dst = g_X0 + (size_t)m * XCOLS + seg * DIM + c4;
    } else if (m < NL0 + NL1) {
        int r = m - NL0;
        if (seg == 0)      v = *reinterpret_cast<const float4*>(h0 + (size_t)idx0[r] * DIM + c4);
        else if (seg == 1) v = *reinterpret_cast<const float4*>(h1 + (size_t)r * DIM + c4);
        dst = g_X1 + (size_t)r * XCOLS + seg * DIM + c4;
    } else {
        int r = m - NL0 - NL1;
        if (seg == 0)      v = *reinterpret_cast<const float4*>(h0 + (size_t)idx0[idx1[r]] * DIM + c4);
        else if (seg == 1) v = *reinterpret_cast<const float4*>(h1 + (size_t)idx1[r] * DIM + c4);
        else               v = *reinterpret_cast<const float4*>(h2 + (size_t)r * DIM + c4);
        dst = g_X2 + (size_t)r * XCOLS + seg * DIM + c4;
    }
    *reinterpret_cast<float4*>(dst) =
        make_float4(tf32r(v.x), tf32r(v.y), tf32r(v.z), tf32r(v.w));
}

// Scatters (unique indices -> no atomics). Runs AFTER fill_x zeroed targets.
__global__ void scatter_kernel(const float* __restrict__ h1, const float* __restrict__ h2,
                               const int* __restrict__ idx0, const int* __restrict__ idx1)
{
    int b = blockIdx.x;        // 0..7999
    int c4 = threadIdx.x << 2;
    float* dst;
    const float* src;
    if (b < NL1) {
        dst = g_X0 + (size_t)idx0[b] * XCOLS + DIM;
        src = h1 + (size_t)b * DIM;
    } else if (b < NL1 + NL2) {
        int r = b - NL1;
        dst = g_X0 + (size_t)idx0[idx1[r]] * XCOLS + 2 * DIM;
        src = h2 + (size_t)r * DIM;
    } else {
        int r = b - NL1 - NL2;
        dst = g_X1 + (size_t)idx1[r] * XCOLS + 2 * DIM;
        src = h2 + (size_t)r * DIM;
    }
    float4 v = *reinterpret_cast<const float4*>(src + c4);
    *reinterpret_cast<float4*>(dst + c4) =
        make_float4(tf32r(v.x), tf32r(v.y), tf32r(v.z), tf32r(v.w));
}

// ---------------- zero the output (fused kernel RED-accumulates into it) ------
__global__ void zero_out_kernel(float* __restrict__ out)
{
    int i = blockIdx.x * blockDim.x + threadIdx.x;
    if (i < (NL0 + NL1 + NL2) * DIM / 4)
        reinterpret_cast<float4*>(out)[i] = make_float4(0.f, 0.f, 0.f, 0.f);
}

// ---------------- fused: out_i += relu((adj_i @ X_i[:,j]) @ W[i,j] + b[i,j]) --
// grid (x = j/n-block 0..2, y = m-block, z = level i). cp.async 3-stage pipeline
// mainloop; epilogue does the 128x128 @ W GEMM in-block then RED-adds to out.
__global__ void __launch_bounds__(256, 2) fused_kernel(
    const float* __restrict__ adj0, const float* __restrict__ adj1,
    const float* __restrict__ adj2, const float* __restrict__ Ws,
    const float* __restrict__ bs, float* __restrict__ out)
{
    const int lvl = blockIdx.z;
    const float* A; const float* Xp; int n, rowoff;
    if (lvl == 0)      { A = adj0; Xp = g_X0; n = NL0; rowoff = 0; }
    else if (lvl == 1) { A = adj1; Xp = g_X1; n = NL1; rowoff = NL0; }
    else               { A = adj2; Xp = g_X2; n = NL2; rowoff = NL0 + NL1; }
    const int bm = blockIdx.y * BM;
    if (bm >= n) return;
    const int j  = blockIdx.x;
    const int bn = j * BN;

    extern __shared__ float sm[];
    const uint32_t sbase = (uint32_t)__cvta_generic_to_shared(sm);

    const int tid  = threadIdx.x;
    const int wid  = tid >> 5;
    const int lane = tid & 31;
    const int wm = (wid >> 2) * 64;
    const int wn = (wid & 3) * 32;
    const int g  = lane >> 2;
    const int t4 = lane & 3;

    // loader coordinates (4 x 16B chunks per thread for each of A and B)
    int arow[4], ac4[4], brow[4], bc4[4];
#pragma unroll
    for (int i4 = 0; i4 < 4; ++i4) {
        int idx = tid + i4 * 256;
        arow[i4] = idx >> 3;        ac4[i4] = (idx & 7) << 2;
        brow[i4] = idx >> 5;        bc4[i4] = (idx & 31) << 2;
    }

    const int K  = n;
    const int KT = (K + BK - 1) / BK;

    auto issue = [&](int kt) {
        const int kbase = kt * BK;
        const uint32_t stb = sbase + (uint32_t)(kt % NSTAGES) * (STAGE_WORDS * 4);
#pragma unroll
        for (int i4 = 0; i4 < 4; ++i4) {
            bool p = (bm + arow[i4] < n) && (kbase + ac4[i4] < K);
            cp16(stb + (arow[i4] * ASTRIDE + ac4[i4]) * 4,
                 A + (size_t)(bm + arow[i4]) * K + kbase + ac4[i4], p);
        }
#pragma unroll
        for (int i4 = 0; i4 < 4; ++i4) {
            bool p = (kbase + brow[i4] < K);
            cp16(stb + (BM * ASTRIDE + brow[i4] * BSTRIDE + bc4[i4]) * 4,
                 Xp + (size_t)(kbase + brow[i4]) * XCOLS + bn + bc4[i4], p);
        }
    };

    float acc[4][4][4];
#pragma unroll
    for (int a = 0; a < 4; a++)
#pragma unroll
        for (int b = 0; b < 4; b++)
#pragma unroll
            for (int c = 0; c < 4; c++) acc[a][b][c] = 0.f;

    issue(0); CP_COMMIT();
    issue(1); CP_COMMIT();

    for (int kt = 0; kt < KT; ++kt) {
        CP_WAIT1();
        __syncthreads();
        if (kt + 2 < KT) issue(kt + 2);
        CP_COMMIT();

        const float* As = sm + (kt % NSTAGES) * STAGE_WORDS;
        const float* Bs = As + BM * ASTRIDE;
#pragma unroll
        for (int ks = 0; ks < 4; ++ks) {
            const int k0 = ks * 8;
            uint32_t af[4][4], bf[4][2];
#pragma unroll
            for (int mt = 0; mt < 4; ++mt) {
                const float* p = &As[(wm + mt * 16 + g) * ASTRIDE + k0 + t4];
                af[mt][0] = f2tf(p[0]);
                af[mt][1] = f2tf(p[8 * ASTRIDE]);
                af[mt][2] = f2tf(p[4]);
                af[mt][3] = f2tf(p[8 * ASTRIDE + 4]);
            }
#pragma unroll
            for (int nt = 0; nt < 4; ++nt) {
                const float* p = &Bs[(k0 + t4) * BSTRIDE + wn + nt * 8 + g];
                bf[nt][0] = __float_as_uint(p[0]);           // X pre-rounded to tf32
                bf[nt][1] = __float_as_uint(p[4 * BSTRIDE]);
            }
#pragma unroll
            for (int mt = 0; mt < 4; ++mt)
#pragma unroll
                for (int nt = 0; nt < 4; ++nt)
                    MMA_TF32(acc[mt][nt], af[mt], bf[nt]);
        }
    }

    CP_WAIT0();
    __syncthreads();   // pipeline smem now reusable

    // ---- epilogue: T = S_tile @ W[lvl,j], relu(T+b) RED-added into out ----
    float* Ae = sm;                       // 128 x AE_STRIDE (tf32 S tile)
    float* We = sm + BM * AE_STRIDE;      // 32 x BSTRIDE (W k-chunk)

#pragma unroll
    for (int mt = 0; mt < 4; ++mt) {
        int r = wm + mt * 16 + g;
#pragma unroll
        for (int nt = 0; nt < 4; ++nt) {
            int c = wn + nt * 8 + 2 * t4;
            Ae[r * AE_STRIDE + c]           = tf32r(acc[mt][nt][0]);
            Ae[r * AE_STRIDE + c + 1]       = tf32r(acc[mt][nt][1]);
            Ae[(r + 8) * AE_STRIDE + c]     = tf32r(acc[mt][nt][2]);
            Ae[(r + 8) * AE_STRIDE + c + 1] = tf32r(acc[mt][nt][3]);
        }
    }

    const float* Wp = Ws + (size_t)(lvl * 3 + j) * DIM * DIM;
    float accT[4][4][4];
#pragma unroll
    for (int a = 0; a < 4; a++)
#pragma unroll
        for (int b = 0; b < 4; b++)
#pragma unroll
            for (int c = 0; c < 4; c++) accT[a][b][c] = 0.f;

    for (int ck = 0; ck < 4; ++ck) {
        __syncthreads();   // Ae ready (ck=0) / previous We consumers done (ck>0)
#pragma unroll
        for (int i4 = 0; i4 < 4; ++i4) {
            int row = brow[i4], c4 = bc4[i4];
            float4 v = *reinterpret_cast<const float4*>(Wp + (size_t)(ck * 32 + row) * DIM + c4);
            We[row * BSTRIDE + c4 + 0] = tf32r(v.x);
            We[row * BSTRIDE + c4 + 1] = tf32r(v.y);
            We[row * BSTRIDE + c4 + 2] = tf32r(v.z);
            We[row * BSTRIDE + c4 + 3] = tf32r(v.w);
        }
        __syncthreads();
#pragma unroll
        for (int ks = 0; ks < 4; ++ks) {
            const int k0 = ks * 8;
            uint32_t af[4][4], bf[4][2];
#pragma unroll
            for (int mt = 0; mt < 4; ++mt) {
                const float* p = &Ae[(wm + mt * 16 + g) * AE_STRIDE + ck * 32 + k0 + t4];
                af[mt][0] = __float_as_uint(p[0]);
                af[mt][1] = __float_as_uint(p[8 * AE_STRIDE]);
                af[mt][2] = __float_as_uint(p[4]);
                af[mt][3] = __float_as_uint(p[8 * AE_STRIDE + 4]);
            }
#pragma unroll
            for (int nt = 0; nt < 4; ++nt) {
                const float* p = &We[(k0 + t4) * BSTRIDE + wn + nt * 8 + g];
                bf[nt][0] = __float_as_uint(p[0]);
                bf[nt][1] = __float_as_uint(p[4 * BSTRIDE]);
            }
#pragma unroll
            for (int mt = 0; mt < 4; ++mt)
#pragma unroll
                for (int nt = 0; nt < 4; ++nt)
                    MMA_TF32(accT[mt][nt], af[mt], bf[nt]);
        }
    }

    const float* bp = bs + (size_t)(lvl * 3 + j) * DIM;
#pragma unroll
    for (int mt = 0; mt < 4; ++mt) {
        int r = bm + wm + mt * 16 + g;
#pragma unroll
        for (int nt = 0; nt < 4; ++nt) {
            int c = wn + nt * 8 + 2 * t4;
            float b0 = bp[c], b1 = bp[c + 1];
            if (r < n) {
                float* o = out + (size_t)(rowoff + r) * DIM + c;
                redadd(o,     fmaxf(accT[mt][nt][0] + b0, 0.f));
                redadd(o + 1, fmaxf(accT[mt][nt][1] + b1, 0.f));
            }
            if (r + 8 < n) {
                float* o = out + (size_t)(rowoff + r + 8) * DIM + c;
                redadd(o,     fmaxf(accT[mt][nt][2] + b0, 0.f));
                redadd(o + 1, fmaxf(accT[mt][nt][3] + b1, 0.f));
            }
        }
    }
}

// ---------------- launch ----------------
extern "C" void kernel_launch(void* const* d_in, const int* in_sizes, int n_in,
                              void* d_out, int out_size)
{
    const float* adj0 = (const float*)d_in[0];
    const float* adj1 = (const float*)d_in[1];
    const float* adj2 = (const float*)d_in[2];
    const float* h0   = (const float*)d_in[3];
    const float* h1   = (const float*)d_in[4];
    const float* h2   = (const float*)d_in[5];
    const int*   idx0 = (const int*)d_in[6];
    const int*   idx1 = (const int*)d_in[7];
    const float* Ws   = (const float*)d_in[8];
    const float* bs   = (const float*)d_in[9];
    float* out = (float*)d_out;

    cudaFuncSetAttribute(fused_kernel, cudaFuncAttributeMaxDynamicSharedMemorySize,
                         SMEM_BYTES);

    fill_x_kernel<<<NL0 + NL1 + NL2, 96>>>(h0, h1, h2, idx0, idx1);
    scatter_kernel<<<NL1 + NL2 + NL2, 32>>>(h1, h2, idx0, idx1);
    zero_out_kernel<<<((NL0 + NL1 + NL2) * DIM / 4 + 255) / 256, 256>>>(out);
    fused_kernel<<<dim3(3, (NL0 + BM - 1) / BM, 3), 256, SMEM_BYTES>>>(
        adj0, adj1, adj2, Ws, bs, out);
}

// round 8
// speedup vs baseline: 1.2993x; 1.1377x over previous
#include <cuda_runtime.h>
#include <cstdint>

#define NL0 8000
#define NL1 4000
#define NL2 2000
#define DIM 128
#define XCOLS 384

#define BM 128
#define BN 128
#define BK 32
#define ASTRIDE 36    // A tile 128x32 padded: frag bank = 4g+t4 -> conflict-free
#define BSTRIDE 136   // B tile 32x128 padded: frag bank = 8t4+g -> conflict-free
#define NSTAGES 3
#define STAGE_WORDS (BM * ASTRIDE + BK * BSTRIDE)   // 8960 words
#define SMEM_WORDS (NSTAGES * STAGE_WORDS)          // 26880 words
#define SMEM_BYTES (SMEM_WORDS * 4)                 // 107520 B
#define AE_STRIDE 132 // epilogue S-tile 128x128 padded

// ---------------- scratch (device globals: allocation-free rule) ----------------
__device__ float g_X0[NL0 * XCOLS];
__device__ float g_X1[NL1 * XCOLS];
__device__ float g_X2[NL2 * XCOLS];

// ---------------- helpers ----------------
__device__ __forceinline__ uint32_t f2tf(float x) {
    uint32_t u;
    asm("cvt.rna.tf32.f32 %0, %1;" : "=r"(u) : "f"(x));
    return u;
}
__device__ __forceinline__ float tf32r(float x) { return __uint_as_float(f2tf(x)); }

__device__ __forceinline__ void cp16(uint32_t dst, const float* src, bool p) {
    int sz = p ? 16 : 0;
    asm volatile("cp.async.cg.shared.global [%0], [%1], 16, %2;\n"
                 :: "r"(dst), "l"(src), "r"(sz));
}
#define CP_COMMIT() asm volatile("cp.async.commit_group;\n")
#define CP_WAIT1()  asm volatile("cp.async.wait_group 1;\n" ::: "memory")
#define CP_WAIT0()  asm volatile("cp.async.wait_group 0;\n" ::: "memory")

__device__ __forceinline__ void redadd(float* p, float v) {
    asm volatile("red.global.add.f32 [%0], %1;" :: "l"(p), "f"(v) : "memory");
}

#define MMA_TF32(d, a, b)                                                        \
    asm volatile(                                                                \
        "mma.sync.aligned.m16n8k8.row.col.f32.tf32.tf32.f32 "                    \
        "{%0,%1,%2,%3}, {%4,%5,%6,%7}, {%8,%9}, {%0,%1,%2,%3};\n"                \
        : "+f"(d[0]), "+f"(d[1]), "+f"(d[2]), "+f"(d[3])                         \
        : "r"(a[0]), "r"(a[1]), "r"(a[2]), "r"(a[3]), "r"(b[0]), "r"(b[1]))

// ---------------- build X_i = [x0->i | x1->i | x2->i] (tf32-prerounded) -------
__global__ void fill_x_kernel(const float* __restrict__ h0, const float* __restrict__ h1,
                              const float* __restrict__ h2, const int* __restrict__ idx0,
                              const int* __restrict__ idx1)
{
    int m = blockIdx.x;
    int t = threadIdx.x;       // 0..95
    int seg = t >> 5;
    int c4 = (t & 31) << 2;
    float4 v = make_float4(0.f, 0.f, 0.f, 0.f);
    float* dst;
    if (m < NL0) {
        if (seg == 0) v = *reinterpret_cast<const float4*>(h0 + (size_t)m * DIM + c4);
        dst = g_X0 + (size_t)m * XCOLS + seg * DIM + c4;
    } else if (m < NL0 + NL1) {
        int r = m - NL0;
        if (seg == 0)      v = *reinterpret_cast<const float4*>(h0 + (size_t)idx0[r] * DIM + c4);
        else if (seg == 1) v = *reinterpret_cast<const float4*>(h1 + (size_t)r * DIM + c4);
        dst = g_X1 + (size_t)r * XCOLS + seg * DIM + c4;
    } else {
        int r = m - NL0 - NL1;
        if (seg == 0)      v = *reinterpret_cast<const float4*>(h0 + (size_t)idx0[idx1[r]] * DIM + c4);
        else if (seg == 1) v = *reinterpret_cast<const float4*>(h1 + (size_t)idx1[r] * DIM + c4);
        else               v = *reinterpret_cast<const float4*>(h2 + (size_t)r * DIM + c4);
        dst = g_X2 + (size_t)r * XCOLS + seg * DIM + c4;
    }
    *reinterpret_cast<float4*>(dst) =
        make_float4(tf32r(v.x), tf32r(v.y), tf32r(v.z), tf32r(v.w));
}

// Scatters (unique indices -> no atomics). Runs AFTER fill_x zeroed targets.
__global__ void scatter_kernel(const float* __restrict__ h1, const float* __restrict__ h2,
                               const int* __restrict__ idx0, const int* __restrict__ idx1)
{
    int b = blockIdx.x;        // 0..7999
    int c4 = threadIdx.x << 2;
    float* dst;
    const float* src;
    if (b < NL1) {
        dst = g_X0 + (size_t)idx0[b] * XCOLS + DIM;
        src = h1 + (size_t)b * DIM;
    } else if (b < NL1 + NL2) {
        int r = b - NL1;
        dst = g_X0 + (size_t)idx0[idx1[r]] * XCOLS + 2 * DIM;
        src = h2 + (size_t)r * DIM;
    } else {
        int r = b - NL1 - NL2;
        dst = g_X1 + (size_t)idx1[r] * XCOLS + 2 * DIM;
        src = h2 + (size_t)r * DIM;
    }
    float4 v = *reinterpret_cast<const float4*>(src + c4);
    *reinterpret_cast<float4*>(dst + c4) =
        make_float4(tf32r(v.x), tf32r(v.y), tf32r(v.z), tf32r(v.w));
}

// ---------------- zero the output (fused kernel RED-accumulates into it) ------
__global__ void zero_out_kernel(float* __restrict__ out)
{
    int i = blockIdx.x * blockDim.x + threadIdx.x;
    if (i < (NL0 + NL1 + NL2) * DIM / 4)
        reinterpret_cast<float4*>(out)[i] = make_float4(0.f, 0.f, 0.f, 0.f);
}

// ---------------- fused: out_i += relu((adj_i @ X_i[:,j]) @ W[i,j] + b[i,j]) --
// 8 warps arranged 4(m) x 2(n): warp tile 32x64. A frag = 8 LDS + 8 CVT,
// B frag = 16 LDS (no CVT, pre-rounded) per k-step -> 2.0 issue slots per MMA.
__global__ void __launch_bounds__(256, 2) fused_kernel(
    const float* __restrict__ adj0, const float* __restrict__ adj1,
    const float* __restrict__ adj2, const float* __restrict__ Ws,
    const float* __restrict__ bs, float* __restrict__ out)
{
    const int lvl = blockIdx.z;
    const float* A; const float* Xp; int n, rowoff;
    if (lvl == 0)      { A = adj0; Xp = g_X0; n = NL0; rowoff = 0; }
    else if (lvl == 1) { A = adj1; Xp = g_X1; n = NL1; rowoff = NL0; }
    else               { A = adj2; Xp = g_X2; n = NL2; rowoff = NL0 + NL1; }
    const int bm = blockIdx.y * BM;
    if (bm >= n) return;
    const int j  = blockIdx.x;
    const int bn = j * BN;

    extern __shared__ float sm[];
    const uint32_t sbase = (uint32_t)__cvta_generic_to_shared(sm);

    const int tid  = threadIdx.x;
    const int wid  = tid >> 5;
    const int lane = tid & 31;
    const int wm = (wid >> 1) * 32;   // warp row base: 0,32,64,96
    const int wn = (wid & 1) * 64;    // warp col base: 0,64
    const int g  = lane >> 2;         // 0..7
    const int t4 = lane & 3;          // 0..3

    // loader coordinates (4 x 16B chunks per thread for each of A and B)
    int arow[4], ac4[4], brow[4], bc4[4];
#pragma unroll
    for (int i4 = 0; i4 < 4; ++i4) {
        int idx = tid + i4 * 256;
        arow[i4] = idx >> 3;        ac4[i4] = (idx & 7) << 2;
        brow[i4] = idx >> 5;        bc4[i4] = (idx & 31) << 2;
    }

    const int K  = n;
    const int KT = (K + BK - 1) / BK;

    auto issue = [&](int kt) {
        const int kbase = kt * BK;
        const uint32_t stb = sbase + (uint32_t)(kt % NSTAGES) * (STAGE_WORDS * 4);
#pragma unroll
        for (int i4 = 0; i4 < 4; ++i4) {
            bool p = (bm + arow[i4] < n) && (kbase + ac4[i4] < K);
            cp16(stb + (arow[i4] * ASTRIDE + ac4[i4]) * 4,
                 A + (size_t)(bm + arow[i4]) * K + kbase + ac4[i4], p);
        }
#pragma unroll
        for (int i4 = 0; i4 < 4; ++i4) {
            bool p = (kbase + brow[i4] < K);
            cp16(stb + (BM * ASTRIDE + brow[i4] * BSTRIDE + bc4[i4]) * 4,
                 Xp + (size_t)(kbase + brow[i4]) * XCOLS + bn + bc4[i4], p);
        }
    };

    float acc[2][8][4];
#pragma unroll
    for (int a = 0; a < 2; a++)
#pragma unroll
        for (int b = 0; b < 8; b++)
#pragma unroll
            for (int c = 0; c < 4; c++) acc[a][b][c] = 0.f;

    issue(0); CP_COMMIT();
    issue(1); CP_COMMIT();

    for (int kt = 0; kt < KT; ++kt) {
        CP_WAIT1();
        __syncthreads();
        if (kt + 2 < KT) issue(kt + 2);
        CP_COMMIT();

        const float* As = sm + (kt % NSTAGES) * STAGE_WORDS;
        const float* Bs = As + BM * ASTRIDE;
#pragma unroll
        for (int ks = 0; ks < 4; ++ks) {
            const int k0 = ks * 8;
            uint32_t af[2][4], bf[8][2];
#pragma unroll
            for (int mt = 0; mt < 2; ++mt) {
                const float* p = &As[(wm + mt * 16 + g) * ASTRIDE + k0 + t4];
                af[mt][0] = f2tf(p[0]);
                af[mt][1] = f2tf(p[8 * ASTRIDE]);
                af[mt][2] = f2tf(p[4]);
                af[mt][3] = f2tf(p[8 * ASTRIDE + 4]);
            }
#pragma unroll
            for (int nt = 0; nt < 8; ++nt) {
                const float* p = &Bs[(k0 + t4) * BSTRIDE + wn + nt * 8 + g];
                bf[nt][0] = __float_as_uint(p[0]);           // X pre-rounded to tf32
                bf[nt][1] = __float_as_uint(p[4 * BSTRIDE]);
            }
#pragma unroll
            for (int mt = 0; mt < 2; ++mt)
#pragma unroll
                for (int nt = 0; nt < 8; ++nt)
                    MMA_TF32(acc[mt][nt], af[mt], bf[nt]);
        }
    }

    CP_WAIT0();
    __syncthreads();   // pipeline smem now reusable

    // ---- epilogue: T = S_tile @ W[lvl,j], relu(T+b) RED-added into out ----
    float* Ae = sm;                       // 128 x AE_STRIDE (tf32 S tile)
    float* We = sm + BM * AE_STRIDE;      // 32 x BSTRIDE (W k-chunk)

#pragma unroll
    for (int mt = 0; mt < 2; ++mt) {
        int r = wm + mt * 16 + g;
#pragma unroll
        for (int nt = 0; nt < 8; ++nt) {
            int c = wn + nt * 8 + 2 * t4;
            Ae[r * AE_STRIDE + c]           = tf32r(acc[mt][nt][0]);
            Ae[r * AE_STRIDE + c + 1]       = tf32r(acc[mt][nt][1]);
            Ae[(r + 8) * AE_STRIDE + c]     = tf32r(acc[mt][nt][2]);
            Ae[(r + 8) * AE_STRIDE + c + 1] = tf32r(acc[mt][nt][3]);
        }
    }

    const float* Wp = Ws + (size_t)(lvl * 3 + j) * DIM * DIM;
    float accT[2][8][4];
#pragma unroll
    for (int a = 0; a < 2; a++)
#pragma unroll
        for (int b = 0; b < 8; b++)
#pragma unroll
            for (int c = 0; c < 4; c++) accT[a][b][c] = 0.f;

    for (int ck = 0; ck < 4; ++ck) {
        __syncthreads();   // Ae ready (ck=0) / previous We consumers done (ck>0)
#pragma unroll
        for (int i4 = 0; i4 < 4; ++i4) {
            int idx = tid + i4 * 256;
            int row = idx >> 5, c4 = (idx & 31) << 2;
            float4 v = *reinterpret_cast<const float4*>(Wp + (size_t)(ck * 32 + row) * DIM + c4);
            We[row * BSTRIDE + c4 + 0] = tf32r(v.x);
            We[row * BSTRIDE + c4 + 1] = tf32r(v.y);
            We[row * BSTRIDE + c4 + 2] = tf32r(v.z);
            We[row * BSTRIDE + c4 + 3] = tf32r(v.w);
        }
        __syncthreads();
#pragma unroll
        for (int ks = 0; ks < 4; ++ks) {
            const int k0 = ks * 8;
            uint32_t af[2][4], bf[8][2];
#pragma unroll
            for (int mt = 0; mt < 2; ++mt) {
                const float* p = &Ae[(wm + mt * 16 + g) * AE_STRIDE + ck * 32 + k0 + t4];
                af[mt][0] = __float_as_uint(p[0]);
                af[mt][1] = __float_as_uint(p[8 * AE_STRIDE]);
                af[mt][2] = __float_as_uint(p[4]);
                af[mt][3] = __float_as_uint(p[8 * AE_STRIDE + 4]);
            }
#pragma unroll
            for (int nt = 0; nt < 8; ++nt) {
                const float* p = &We[(k0 + t4) * BSTRIDE + wn + nt * 8 + g];
                bf[nt][0] = __float_as_uint(p[0]);
                bf[nt][1] = __float_as_uint(p[4 * BSTRIDE]);
            }
#pragma unroll
            for (int mt = 0; mt < 2; ++mt)
#pragma unroll
                for (int nt = 0; nt < 8; ++nt)
                    MMA_TF32(accT[mt][nt], af[mt], bf[nt]);
        }
    }

    const float* bp = bs + (size_t)(lvl * 3 + j) * DIM;
#pragma unroll
    for (int mt = 0; mt < 2; ++mt) {
        int r = bm + wm + mt * 16 + g;
#pragma unroll
        for (int nt = 0; nt < 8; ++nt) {
            int c = wn + nt * 8 + 2 * t4;
            float b0 = bp[c], b1 = bp[c + 1];
            if (r < n) {
                float* o = out + (size_t)(rowoff + r) * DIM + c;
                redadd(o,     fmaxf(accT[mt][nt][0] + b0, 0.f));
                redadd(o + 1, fmaxf(accT[mt][nt][1] + b1, 0.f));
            }
            if (r + 8 < n) {
                float* o = out + (size_t)(rowoff + r + 8) * DIM + c;
                redadd(o,     fmaxf(accT[mt][nt][2] + b0, 0.f));
                redadd(o + 1, fmaxf(accT[mt][nt][3] + b1, 0.f));
            }
        }
    }
}

// ---------------- launch ----------------
extern "C" void kernel_launch(void* const* d_in, const int* in_sizes, int n_in,
                              void* d_out, int out_size)
{
    const float* adj0 = (const float*)d_in[0];
    const float* adj1 = (const float*)d_in[1];
    const float* adj2 = (const float*)d_in[2];
    const float* h0   = (const float*)d_in[3];
    const float* h1   = (const float*)d_in[4];
    const float* h2   = (const float*)d_in[5];
    const int*   idx0 = (const int*)d_in[6];
    const int*   idx1 = (const int*)d_in[7];
    const float* Ws   = (const float*)d_in[8];
    const float* bs   = (const float*)d_in[9];
    float* out = (float*)d_out;

    cudaFuncSetAttribute(fused_kernel, cudaFuncAttributeMaxDynamicSharedMemorySize,
                         SMEM_BYTES);

    fill_x_kernel<<<NL0 + NL1 + NL2, 96>>>(h0, h1, h2, idx0, idx1);
    scatter_kernel<<<NL1 + NL2 + NL2, 32>>>(h1, h2, idx0, idx1);
    zero_out_kernel<<<((NL0 + NL1 + NL2) * DIM / 4 + 255) / 256, 256>>>(out);
    fused_kernel<<<dim3(3, (NL0 + BM - 1) / BM, 3), 256, SMEM_BYTES>>>(
        adj0, adj1, adj2, Ws, bs, out);
}